// round 16
// baseline (speedup 1.0000x reference)
#include <cuda_runtime.h>
#include <cuda_fp16.h>
#include <cstdint>
#include <cstddef>

// ---------------------------------------------------------------------------
// SingleStreamBlock: B=2, L=2048, H=2048, NH=16, D=128, MLP=8192
// fp16 tensor cores; fused qkv epilogue (rmsnorm+rope); paired-tile flash;
// dual-stream weight conversion; silu-in-smem mod; simplified graph
// ---------------------------------------------------------------------------
#define BB   2
#define LL   2048
#define HH   2048
#define NHH  16
#define DD   128
#define MLPD 8192
#define H3   6144
#define HC1  14336
#define HC2  10240

// ------------------------- scratch (device globals) ------------------------
__device__ float  g_mod   [BB * H3];
__device__ __half g_xmodh [(size_t)BB * LL * HH];
__device__ __half g_qh    [(size_t)BB * NHH * LL * DD];   // scaled by log2e/sqrt(D)
__device__ __half g_kh    [(size_t)BB * NHH * LL * DD];
__device__ __half g_vh    [(size_t)BB * LL * HH];         // compact V [b][l][n*D+hc]
__device__ __half g_cath  [(size_t)BB * LL * HC2];        // attn|gelu
__device__ __half g_w1h   [(size_t)HC1 * HH];
__device__ __half g_w2h   [(size_t)HH * HC2];

// ------------------------------ helpers ------------------------------------
__device__ __forceinline__ uint32_t smem_u32(const void* p) {
    uint32_t a;
    asm("{ .reg .u64 t; cvta.to.shared.u64 t, %1; cvt.u32.u64 %0, t; }"
        : "=r"(a) : "l"(p));
    return a;
}

__device__ __forceinline__ void cp16(uint32_t s, const void* g) {
    asm volatile("cp.async.cg.shared.global [%0], [%1], 16;" :: "r"(s), "l"(g));
}

__device__ __forceinline__ void ldsm4(uint32_t* r, uint32_t addr) {
    asm volatile("ldmatrix.sync.aligned.m8n8.x4.shared.b16 {%0,%1,%2,%3}, [%4];"
        : "=r"(r[0]), "=r"(r[1]), "=r"(r[2]), "=r"(r[3]) : "r"(addr));
}

__device__ __forceinline__ void ldsm4t(uint32_t* r, uint32_t addr) {
    asm volatile("ldmatrix.sync.aligned.m8n8.x4.trans.shared.b16 {%0,%1,%2,%3}, [%4];"
        : "=r"(r[0]), "=r"(r[1]), "=r"(r[2]), "=r"(r[3]) : "r"(addr));
}

__device__ __forceinline__ void mma16816(float* d, const uint32_t* a, const uint32_t* b) {
    asm volatile(
        "mma.sync.aligned.m16n8k16.row.col.f32.f16.f16.f32 "
        "{%0,%1,%2,%3}, {%4,%5,%6,%7}, {%8,%9}, {%0,%1,%2,%3};"
        : "+f"(d[0]), "+f"(d[1]), "+f"(d[2]), "+f"(d[3])
        : "r"(a[0]), "r"(a[1]), "r"(a[2]), "r"(a[3]), "r"(b[0]), "r"(b[1]));
}

// ============ fp16 GEMM, 128x256 CTA tile, 256 thr, 64x64 warp tiles ========
// C[M,N] = A[M,K] @ B[N,K]^T
// EPI 2: fused qkv epilogue: q/k -> rmsnorm+rope -> g_qh/g_kh; v -> g_vh
// EPI 3: C fp32 = xres + gate*(v + bias[c])
// EPI 4: C half = gelu(v + bias[c])
#define GBM 128
#define GBN 256
#define GBK 64
#define GSTG 4
#define GA_BYTES (GBM * 128)
#define GB_BYTES (GBN * 128)
#define GSTAGE (GA_BYTES + GB_BYTES)
#define GSMEM (GSTG * GSTAGE)         // 196608

__device__ __forceinline__ void gstage_load(uint32_t sbuf,
                                            const __half* __restrict__ A, int lda,
                                            const __half* __restrict__ B, int ldb,
                                            int m0, int n0, int kt, int tid) {
    const __half* Ab = A + (size_t)m0 * lda + kt * GBK;
#pragma unroll
    for (int i = 0; i < 4; i++) {
        int idx = tid + i * 256;
        int r = idx >> 3, c = idx & 7;
        cp16(sbuf + r * 128 + ((c << 4) ^ ((r & 7) << 4)),
             Ab + (size_t)r * lda + c * 8);
    }
    const __half* Bb = B + (size_t)n0 * ldb + kt * GBK;
#pragma unroll
    for (int i = 0; i < 8; i++) {
        int idx = tid + i * 256;
        int r = idx >> 3, c = idx & 7;
        cp16(sbuf + GA_BYTES + r * 128 + ((c << 4) ^ ((r & 7) << 4)),
             Bb + (size_t)r * ldb + c * 8);
    }
}

template<int EPI>
__global__ __launch_bounds__(256, 1) void hgemm(
    const __half* __restrict__ A, int lda,
    const __half* __restrict__ B, int ldb,
    void* __restrict__ Cg, int ldc,
    int K,
    const float* __restrict__ bias,
    const float* __restrict__ xres,
    const float* __restrict__ pe,
    const float* __restrict__ qsc,
    const float* __restrict__ ksc)
{
    extern __shared__ char smem_raw[];
    uint32_t sb = smem_u32(smem_raw);
    int tid = threadIdx.x, lane = tid & 31, w = tid >> 5;
    int wm = w >> 2, wn = w & 3;                 // 2x4 warps, warp tile 64x64

    int m0 = blockIdx.y * GBM;
    int n0 = blockIdx.x * GBN;
    int nkt = K / GBK;

#pragma unroll
    for (int t = 0; t < GSTG - 1; t++) {
        gstage_load(sb + t * GSTAGE, A, lda, B, ldb, m0, n0, t, tid);
        asm volatile("cp.async.commit_group;" ::: "memory");
    }

    float acc[4][8][4];
#pragma unroll
    for (int mi = 0; mi < 4; mi++)
#pragma unroll
        for (int ni = 0; ni < 8; ni++)
#pragma unroll
            for (int e = 0; e < 4; e++) acc[mi][ni][e] = 0.f;

    int l15 = lane & 15;
    uint32_t khi = (lane >> 4) << 4;
    uint32_t aoff[4], amask[4];
#pragma unroll
    for (int mi = 0; mi < 4; mi++) {
        int row = wm * 64 + mi * 16 + l15;
        aoff[mi]  = row * 128;
        amask[mi] = (row & 7) << 4;
    }
    uint32_t boff[4], bmask[4];
#pragma unroll
    for (int p = 0; p < 4; p++) {
        int row = wn * 64 + p * 16 + l15;
        boff[p]  = GA_BYTES + row * 128;
        bmask[p] = (row & 7) << 4;
    }

    for (int kt = 0; kt < nkt; kt++) {
        int pend = nkt - kt - 1;
        if (pend > GSTG - 2) pend = GSTG - 2;
        if (pend == 2)      asm volatile("cp.async.wait_group 2;" ::: "memory");
        else if (pend == 1) asm volatile("cp.async.wait_group 1;" ::: "memory");
        else                asm volatile("cp.async.wait_group 0;" ::: "memory");
        __syncthreads();

        int tl = kt + GSTG - 1;
        if (tl < nkt) {
            gstage_load(sb + (tl & (GSTG - 1)) * GSTAGE, A, lda, B, ldb, m0, n0, tl, tid);
            asm volatile("cp.async.commit_group;" ::: "memory");
        }

        uint32_t sA = sb + (kt & (GSTG - 1)) * GSTAGE;
#pragma unroll
        for (int ks = 0; ks < 4; ks++) {
            uint32_t kb = ks * 32 + khi;
            uint32_t a[4][4];
#pragma unroll
            for (int mi = 0; mi < 4; mi++)
                ldsm4(a[mi], sA + aoff[mi] + (kb ^ amask[mi]));
            uint32_t bf[8][2];
#pragma unroll
            for (int p = 0; p < 4; p++) {
                uint32_t r[4];
                ldsm4(r, sA + boff[p] + (kb ^ bmask[p]));
                bf[2 * p][0]     = r[0];
                bf[2 * p + 1][0] = r[1];
                bf[2 * p][1]     = r[2];
                bf[2 * p + 1][1] = r[3];
            }
#pragma unroll
            for (int mi = 0; mi < 4; mi++)
#pragma unroll
                for (int ni = 0; ni < 8; ni++)
                    mma16816(acc[mi][ni], a[mi], bf[ni]);
        }
    }

    int rb = m0 + wm * 64, nb = n0 + wn * 64;
    int r0 = lane >> 2, c0 = (lane & 3) * 2;
    if (EPI == 3) {
        float* C = (float*)Cg;
#pragma unroll
        for (int mi = 0; mi < 4; mi++) {
#pragma unroll
            for (int ni = 0; ni < 8; ni++) {
                int r = rb + mi * 16 + r0;
                int c = nb + ni * 8 + c0;
                int bt = r >> 11;
                float g0 = g_mod[bt * H3 + 2 * HH + c];
                float g1 = g_mod[bt * H3 + 2 * HH + c + 1];
                float b0 = bias[c], b1 = bias[c + 1];
                C[(size_t)r * ldc + c]           = xres[(size_t)r * ldc + c]           + g0 * (acc[mi][ni][0] + b0);
                C[(size_t)r * ldc + c + 1]       = xres[(size_t)r * ldc + c + 1]       + g1 * (acc[mi][ni][1] + b1);
                C[(size_t)(r + 8) * ldc + c]     = xres[(size_t)(r + 8) * ldc + c]     + g0 * (acc[mi][ni][2] + b0);
                C[(size_t)(r + 8) * ldc + c + 1] = xres[(size_t)(r + 8) * ldc + c + 1] + g1 * (acc[mi][ni][3] + b1);
            }
        }
    } else if (EPI == 2) {
        if (n0 >= 4096) {
            // ---- V region: plain bias, compact layout ----
#pragma unroll
            for (int mi = 0; mi < 4; mi++) {
#pragma unroll
                for (int ni = 0; ni < 8; ni++) {
                    int r = rb + mi * 16 + r0;
                    int c = nb + ni * 8 + c0;
                    float b0 = bias[c], b1 = bias[c + 1];
                    int bb = r >> 11, l = r & 2047;
                    *(__half2*)(g_vh + (size_t)(bb * LL + l) * HH + (c - 4096)) =
                        __floats2half2_rn(acc[mi][ni][0] + b0, acc[mi][ni][1] + b1);
                    *(__half2*)(g_vh + (size_t)(bb * LL + l + 8) * HH + (c - 4096)) =
                        __floats2half2_rn(acc[mi][ni][2] + b0, acc[mi][ni][3] + b1);
                }
            }
        } else {
            // ---- q/k region: rmsnorm + rope fused ----
            __syncthreads();
            float* sums = (float*)smem_raw;        // [128][4]
            int isK = (n0 >= 2048);
#pragma unroll
            for (int mi = 0; mi < 4; mi++) {
                float s0 = 0.f, s1 = 0.f;
#pragma unroll
                for (int ni = 0; ni < 8; ni++) {
                    int c = nb + ni * 8 + c0;
                    float b0 = bias[c], b1 = bias[c + 1];
                    float v0 = acc[mi][ni][0] + b0, v1 = acc[mi][ni][1] + b1;
                    float v2 = acc[mi][ni][2] + b0, v3 = acc[mi][ni][3] + b1;
                    s0 += v0 * v0 + v1 * v1;
                    s1 += v2 * v2 + v3 * v3;
                }
                s0 += __shfl_xor_sync(0xffffffffu, s0, 1);
                s0 += __shfl_xor_sync(0xffffffffu, s0, 2);
                s1 += __shfl_xor_sync(0xffffffffu, s1, 1);
                s1 += __shfl_xor_sync(0xffffffffu, s1, 2);
                if ((lane & 3) == 0) {
                    sums[(wm * 64 + mi * 16 + r0) * 4 + wn]     = s0;
                    sums[(wm * 64 + mi * 16 + r0 + 8) * 4 + wn] = s1;
                }
            }
            __syncthreads();
            const float* scp = isK ? ksc : qsc;
            int hbase = (nb - (isK ? 2048 : 0)) >> 7;
            float qmul = isK ? 1.f : (0.08838834764831845f * 1.4426950408889634f);
            __half* base = isK ? g_kh : g_qh;
#pragma unroll
            for (int mi = 0; mi < 4; mi++) {
#pragma unroll
                for (int e = 0; e < 2; e++) {
                    int r = rb + mi * 16 + r0 + e * 8;
                    int lrow = wm * 64 + mi * 16 + r0 + e * 8;
                    float tot = sums[lrow * 4 + wn] + sums[lrow * 4 + (wn ^ 1)];
                    float rstd = rsqrtf(tot * (1.f / DD) + 1e-6f) * qmul;
                    int bb = r >> 11, l = r & 2047;
                    const float* peb = pe + (size_t)(bb * LL + l) * (DD / 2) * 4;
                    __half* dst = base + ((size_t)(bb * NHH + hbase) * LL + l) * DD;
#pragma unroll
                    for (int ni = 0; ni < 8; ni++) {
                        int c = nb + ni * 8 + c0;
                        int hc = c & 127;
                        float v0 = (acc[mi][ni][e ? 2 : 0] + bias[c])     * rstd * scp[hc];
                        float v1 = (acc[mi][ni][e ? 3 : 1] + bias[c + 1]) * rstd * scp[hc + 1];
                        const float4 p4 = *(const float4*)(peb + (hc >> 1) * 4);
                        float o0 = p4.x * v0 + p4.y * v1;
                        float o1 = p4.z * v0 + p4.w * v1;
                        *(__half2*)(dst + hc) = __floats2half2_rn(o0, o1);
                    }
                }
            }
        }
    } else {
        __half* C = (__half*)Cg;
#pragma unroll
        for (int mi = 0; mi < 4; mi++) {
#pragma unroll
            for (int ni = 0; ni < 8; ni++) {
                int r = rb + mi * 16 + r0;
                int c = nb + ni * 8 + c0;
                float b0 = bias[c], b1 = bias[c + 1];
                float v0 = acc[mi][ni][0] + b0, v1 = acc[mi][ni][1] + b1;
                float v2 = acc[mi][ni][2] + b0, v3 = acc[mi][ni][3] + b1;
                if (EPI == 4) {
                    float t0 = 0.7978845608028654f * (v0 + 0.044715f * v0 * v0 * v0);
                    float t1 = 0.7978845608028654f * (v1 + 0.044715f * v1 * v1 * v1);
                    float t2 = 0.7978845608028654f * (v2 + 0.044715f * v2 * v2 * v2);
                    float t3 = 0.7978845608028654f * (v3 + 0.044715f * v3 * v3 * v3);
                    v0 = 0.5f * v0 * (1.f + tanhf(t0));
                    v1 = 0.5f * v1 * (1.f + tanhf(t1));
                    v2 = 0.5f * v2 * (1.f + tanhf(t2));
                    v3 = 0.5f * v3 * (1.f + tanhf(t3));
                }
                *(__half2*)(C + (size_t)r * ldc + c)       = __floats2half2_rn(v0, v1);
                *(__half2*)(C + (size_t)(r + 8) * ldc + c) = __floats2half2_rn(v2, v3);
            }
        }
    }
}

// ================== flash attention v3: paired-tile softmax =================
#define FKT 64
#define FK_BYTES 16384
#define FNBUF 6
#define FSM_K0 32768
#define FSM_V0 (32768 + FNBUF * FK_BYTES)
#define FSMEM  (32768 + 2 * FNBUF * FK_BYTES)        // 229376

__device__ __forceinline__ uint32_t swoff(int row, int c) {
    return (uint32_t)(row * 256 + ((c >> 3) << 7) + (((c & 7) ^ (row & 7)) << 4));
}

__global__ __launch_bounds__(256, 1) void flash_kernel() {
    extern __shared__ char fsm[];
    uint32_t sb = smem_u32(fsm);
    int tid = threadIdx.x, lane = tid & 31, w = tid >> 5;
    int q0 = blockIdx.x * 128;
    int bh = blockIdx.y;
    int b = bh >> 4, h = bh & 15;

    const __half* Qg = g_qh + ((size_t)bh * LL + q0) * DD;
    const __half* Kg = g_kh + (size_t)bh * LL * DD;
    const __half* Vg = g_vh + (size_t)b * LL * HH + h * DD;

    int lr = tid >> 4, lc = tid & 15;

    {
#pragma unroll
        for (int i = 0; i < 8; i++) {
            int r = lr + i * 16;
            cp16(sb + swoff(r, lc), Qg + (size_t)r * DD + lc * 8);
        }
        asm volatile("cp.async.commit_group;" ::: "memory");
    }

#pragma unroll
    for (int t = 0; t < 4; t++) {
        const __half* Kt = Kg + (size_t)t * FKT * DD;
        const __half* Vt = Vg + (size_t)t * FKT * HH;
        uint32_t kdst = sb + FSM_K0 + t * FK_BYTES;
        uint32_t vdst = sb + FSM_V0 + t * FK_BYTES;
#pragma unroll
        for (int i = 0; i < 4; i++) {
            int r = lr + i * 16;
            cp16(kdst + swoff(r, lc), Kt + (size_t)r * DD + lc * 8);
            cp16(vdst + swoff(r, lc), Vt + (size_t)r * HH + lc * 8);
        }
        asm volatile("cp.async.commit_group;" ::: "memory");
    }

    asm volatile("cp.async.wait_group 4;" ::: "memory");
    __syncthreads();

    int l15 = lane & 15;
    int qrow = w * 16 + l15;
    uint32_t qf[8][4];
#pragma unroll
    for (int ks = 0; ks < 8; ks++) {
        int cq = ks * 2 + (lane >> 4);
        ldsm4(qf[ks], sb + swoff(qrow, cq));
    }

    uint32_t voff[8];
#pragma unroll
    for (int p = 0; p < 8; p++) {
        int nc = p * 2 + (lane >> 4);
        voff[p] = (uint32_t)(((nc >> 3) << 7) + (((nc & 7) ^ (l15 & 7)) << 4) + l15 * 256);
    }

    float accO[16][4];
#pragma unroll
    for (int nt = 0; nt < 16; nt++)
#pragma unroll
        for (int e = 0; e < 4; e++) accO[nt][e] = 0.f;
    float m0 = -1e30f, m1 = -1e30f, l0 = 0.f, l1 = 0.f;

    const int NT = LL / FKT;     // 32 tiles, 16 pairs
    for (int pj = 0; pj < NT; pj += 2) {
        if (pj + 2 < NT) asm volatile("cp.async.wait_group 2;" ::: "memory");
        else             asm volatile("cp.async.wait_group 0;" ::: "memory");
        __syncthreads();

        if (pj + 4 < NT) {
#pragma unroll
            for (int t = 0; t < 2; t++) {
                int tl = pj + 4 + t;
                const __half* Kt = Kg + (size_t)tl * FKT * DD;
                const __half* Vt = Vg + (size_t)tl * FKT * HH;
                uint32_t kdst = sb + FSM_K0 + (tl % FNBUF) * FK_BYTES;
                uint32_t vdst = sb + FSM_V0 + (tl % FNBUF) * FK_BYTES;
#pragma unroll
                for (int i = 0; i < 4; i++) {
                    int r = lr + i * 16;
                    cp16(kdst + swoff(r, lc), Kt + (size_t)r * DD + lc * 8);
                    cp16(vdst + swoff(r, lc), Vt + (size_t)r * HH + lc * 8);
                }
                asm volatile("cp.async.commit_group;" ::: "memory");
            }
        }

        uint32_t kb0 = sb + FSM_K0 + (pj % FNBUF) * FK_BYTES;
        uint32_t kb1 = sb + FSM_K0 + ((pj + 1) % FNBUF) * FK_BYTES;
        uint32_t vb0 = sb + FSM_V0 + (pj % FNBUF) * FK_BYTES;
        uint32_t vb1 = sb + FSM_V0 + ((pj + 1) % FNBUF) * FK_BYTES;

        float accS[16][4];
#pragma unroll
        for (int nt = 0; nt < 16; nt++)
#pragma unroll
            for (int e = 0; e < 4; e++) accS[nt][e] = 0.f;

#pragma unroll
        for (int ks = 0; ks < 8; ks++) {
            int cq = ks * 2 + (lane >> 4);
            uint32_t cpart = (uint32_t)(((cq >> 3) << 7) + ((cq & 7) << 4));
#pragma unroll
            for (int half = 0; half < 2; half++) {
                uint32_t kbh = half ? kb1 : kb0;
#pragma unroll
                for (int p = 0; p < 4; p++) {
                    int krow = p * 16 + l15;
                    uint32_t r[4];
                    ldsm4(r, kbh + (uint32_t)(krow * 256)
                              + (cpart ^ ((uint32_t)(krow & 7) << 4)));
                    uint32_t b0[2] = { r[0], r[2] }, b1[2] = { r[1], r[3] };
                    mma16816(accS[half * 8 + 2 * p],     qf[ks], b0);
                    mma16816(accS[half * 8 + 2 * p + 1], qf[ks], b1);
                }
            }
        }

        float rmax0 = accS[0][0], rmax1 = accS[0][2];
#pragma unroll
        for (int nt = 0; nt < 16; nt++) {
            rmax0 = fmaxf(rmax0, fmaxf(accS[nt][0], accS[nt][1]));
            rmax1 = fmaxf(rmax1, fmaxf(accS[nt][2], accS[nt][3]));
        }
        rmax0 = fmaxf(rmax0, __shfl_xor_sync(0xffffffffu, rmax0, 1));
        rmax0 = fmaxf(rmax0, __shfl_xor_sync(0xffffffffu, rmax0, 2));
        rmax1 = fmaxf(rmax1, __shfl_xor_sync(0xffffffffu, rmax1, 1));
        rmax1 = fmaxf(rmax1, __shfl_xor_sync(0xffffffffu, rmax1, 2));

        float mn0 = fmaxf(m0, rmax0), mn1 = fmaxf(m1, rmax1);
        float al0 = exp2f(m0 - mn0), al1 = exp2f(m1 - mn1);
        m0 = mn0; m1 = mn1;

        float rs0 = 0.f, rs1 = 0.f;
#pragma unroll
        for (int nt = 0; nt < 16; nt++) {
            accS[nt][0] = exp2f(accS[nt][0] - mn0);
            accS[nt][1] = exp2f(accS[nt][1] - mn0);
            accS[nt][2] = exp2f(accS[nt][2] - mn1);
            accS[nt][3] = exp2f(accS[nt][3] - mn1);
            rs0 += accS[nt][0] + accS[nt][1];
            rs1 += accS[nt][2] + accS[nt][3];
        }
        rs0 += __shfl_xor_sync(0xffffffffu, rs0, 1);
        rs0 += __shfl_xor_sync(0xffffffffu, rs0, 2);
        rs1 += __shfl_xor_sync(0xffffffffu, rs1, 1);
        rs1 += __shfl_xor_sync(0xffffffffu, rs1, 2);
        l0 = l0 * al0 + rs0;
        l1 = l1 * al1 + rs1;

#pragma unroll
        for (int nt = 0; nt < 16; nt++) {
            accO[nt][0] *= al0; accO[nt][1] *= al0;
            accO[nt][2] *= al1; accO[nt][3] *= al1;
        }

#pragma unroll
        for (int half = 0; half < 2; half++) {
            uint32_t vbh = half ? vb1 : vb0;
#pragma unroll
            for (int kc = 0; kc < 4; kc++) {
                int s0i = half * 8 + 2 * kc;
                uint32_t pf[4];
                {
                    __half2 h0 = __floats2half2_rn(accS[s0i][0],     accS[s0i][1]);
                    __half2 h1 = __floats2half2_rn(accS[s0i][2],     accS[s0i][3]);
                    __half2 h2 = __floats2half2_rn(accS[s0i + 1][0], accS[s0i + 1][1]);
                    __half2 h3 = __floats2half2_rn(accS[s0i + 1][2], accS[s0i + 1][3]);
                    pf[0] = *(uint32_t*)&h0; pf[1] = *(uint32_t*)&h1;
                    pf[2] = *(uint32_t*)&h2; pf[3] = *(uint32_t*)&h3;
                }
                uint32_t vrow = vbh + (uint32_t)(kc * 4096);
#pragma unroll
                for (int p = 0; p < 8; p++) {
                    uint32_t r[4];
                    ldsm4t(r, vrow + voff[p]);
                    uint32_t b0[2] = { r[0], r[1] }, b1[2] = { r[2], r[3] };
                    mma16816(accO[2 * p],     pf, b0);
                    mma16816(accO[2 * p + 1], pf, b1);
                }
            }
        }
    }

    float i0 = 1.f / l0, i1 = 1.f / l1;
    int r0g = q0 + w * 16 + (lane >> 2);
    int cb  = h * DD + (lane & 3) * 2;
#pragma unroll
    for (int nt = 0; nt < 16; nt++) {
        int col = cb + nt * 8;
        *(__half2*)(g_cath + (size_t)(b * LL + r0g) * HC2 + col) =
            __floats2half2_rn(accO[nt][0] * i0, accO[nt][1] * i0);
        *(__half2*)(g_cath + (size_t)(b * LL + r0g + 8) * HC2 + col) =
            __floats2half2_rn(accO[nt][2] * i1, accO[nt][3] * i1);
    }
}

// ---------------------- weight fp32 -> fp16 convert -------------------------
__global__ void cvt_half_kernel(const float4* __restrict__ src,
                                __half2* __restrict__ dst, int n4) {
    int i = blockIdx.x * blockDim.x + threadIdx.x;
    if (i >= n4) return;
    float4 v = src[i];
    dst[2 * i]     = __floats2half2_rn(v.x, v.y);
    dst[2 * i + 1] = __floats2half2_rn(v.z, v.w);
}

// ---- K0: mod = silu(vec) @ mod_w^T + mod_b  (silu staged in smem) ----------
__global__ void mod_gemm_kernel(const float* __restrict__ vec,
                                const float* __restrict__ mod_w,
                                const float* __restrict__ mod_b) {
    __shared__ float sv[HH];
    int tid = threadIdx.x, lane = tid & 31;
    int b = (blockIdx.x * 8) / H3;                 // 8 outputs per CTA
    const float4* vr = (const float4*)(vec + (size_t)b * HH);
#pragma unroll
    for (int i = tid; i < HH / 4; i += 256) {
        float4 v = vr[i];
        float4 o;
        o.x = v.x / (1.f + expf(-v.x));
        o.y = v.y / (1.f + expf(-v.y));
        o.z = v.z / (1.f + expf(-v.z));
        o.w = v.w / (1.f + expf(-v.w));
        ((float4*)sv)[i] = o;
    }
    __syncthreads();

    int j = (blockIdx.x * 8 + (tid >> 5)) % H3;
    const float4* wr = (const float4*)(mod_w + (size_t)j * HH);
    const float4* sv4 = (const float4*)sv;
    float acc = 0.f;
#pragma unroll 4
    for (int k = lane; k < HH / 4; k += 32) {
        float4 v = sv4[k];
        float4 ww = wr[k];
        acc += v.x * ww.x + v.y * ww.y + v.z * ww.z + v.w * ww.w;
    }
#pragma unroll
    for (int o = 16; o; o >>= 1) acc += __shfl_xor_sync(0xffffffffu, acc, o);
    if (lane == 0) g_mod[b * H3 + j] = acc + mod_b[j];
}

// -------- K1: x_mod = (1+scale)*LN(x) + shift  (float4 in, fp16 out) --------
__global__ void ln_mod_kernel(const float* __restrict__ x) {
    __shared__ float red[32];
    __shared__ float bval[2];
    int row = blockIdx.x;
    int tid = threadIdx.x;
    int lane = tid & 31, wid = tid >> 5;
    const float4* xr4 = (const float4*)(x + (size_t)row * HH);

    float4 v[2];
    v[0] = xr4[tid];
    v[1] = xr4[tid + 256];
    float s = v[0].x + v[0].y + v[0].z + v[0].w
            + v[1].x + v[1].y + v[1].z + v[1].w;
#pragma unroll
    for (int o = 16; o; o >>= 1) s += __shfl_xor_sync(0xffffffffu, s, o);
    if (lane == 0) red[wid] = s;
    __syncthreads();
    if (tid < 32) {
        float r = (tid < 8) ? red[tid] : 0.f;
#pragma unroll
        for (int o = 4; o; o >>= 1) r += __shfl_xor_sync(0xffffffffu, r, o);
        if (tid == 0) bval[0] = r;
    }
    __syncthreads();
    float mu = bval[0] * (1.f / HH);

    float sq = 0.f;
#pragma unroll
    for (int i = 0; i < 2; i++) {
        float d0 = v[i].x - mu, d1 = v[i].y - mu;
        float d2 = v[i].z - mu, d3 = v[i].w - mu;
        sq += d0 * d0 + d1 * d1 + d2 * d2 + d3 * d3;
    }
#pragma unroll
    for (int o = 16; o; o >>= 1) sq += __shfl_xor_sync(0xffffffffu, sq, o);
    __syncthreads();
    if (lane == 0) red[wid] = sq;
    __syncthreads();
    if (tid < 32) {
        float r = (tid < 8) ? red[tid] : 0.f;
#pragma unroll
        for (int o = 4; o; o >>= 1) r += __shfl_xor_sync(0xffffffffu, r, o);
        if (tid == 0) bval[1] = r;
    }
    __syncthreads();
    float rstd = rsqrtf(bval[1] * (1.f / HH) + 1e-6f);

    int b = row >> 11;
#pragma unroll
    for (int i = 0; i < 2; i++) {
        int c = (tid + i * 256) * 4;
        float4 sc4 = *(const float4*)(g_mod + b * H3 + HH + c);
        float4 sh4 = *(const float4*)(g_mod + b * H3 + c);
        float o0 = (1.f + sc4.x) * ((v[i].x - mu) * rstd) + sh4.x;
        float o1 = (1.f + sc4.y) * ((v[i].y - mu) * rstd) + sh4.y;
        float o2 = (1.f + sc4.z) * ((v[i].z - mu) * rstd) + sh4.z;
        float o3 = (1.f + sc4.w) * ((v[i].w - mu) * rstd) + sh4.w;
        uint2 o;
        *(__half2*)&o.x = __floats2half2_rn(o0, o1);
        *(__half2*)&o.y = __floats2half2_rn(o2, o3);
        *(uint2*)(g_xmodh + (size_t)row * HH + c) = o;
    }
}

// ---------------------------------------------------------------------------
extern "C" void kernel_launch(void* const* d_in, const int* in_sizes, int n_in,
                              void* d_out, int out_size) {
    const float* x       = (const float*)d_in[0];
    const float* vec     = (const float*)d_in[1];
    const float* pe      = (const float*)d_in[2];
    const float* mod_w   = (const float*)d_in[3];
    const float* mod_b   = (const float*)d_in[4];
    const float* lin1_w  = (const float*)d_in[5];
    const float* lin1_b  = (const float*)d_in[6];
    const float* lin2_w  = (const float*)d_in[7];
    const float* lin2_b  = (const float*)d_in[8];
    const float* q_scale = (const float*)d_in[9];
    const float* k_scale = (const float*)d_in[10];
    float* out = (float*)d_out;

    void* tmp;
    cudaGetSymbolAddress(&tmp, g_xmodh);  __half* p_xmod = (__half*)tmp;
    cudaGetSymbolAddress(&tmp, g_cath);   __half* p_cat  = (__half*)tmp;
    cudaGetSymbolAddress(&tmp, g_qh);     __half* p_q    = (__half*)tmp;
    cudaGetSymbolAddress(&tmp, g_w1h);    __half* p_w1   = (__half*)tmp;
    cudaGetSymbolAddress(&tmp, g_w2h);    __half* p_w2   = (__half*)tmp;

    static cudaStream_t s1 = nullptr, s2 = nullptr;
    static cudaEvent_t eFork, eW1a, eW2, eXmod, eK2b;
    static int attr_set = 0;
    if (!attr_set) {
        cudaFuncSetAttribute(hgemm<2>, cudaFuncAttributeMaxDynamicSharedMemorySize, GSMEM);
        cudaFuncSetAttribute(hgemm<3>, cudaFuncAttributeMaxDynamicSharedMemorySize, GSMEM);
        cudaFuncSetAttribute(hgemm<4>, cudaFuncAttributeMaxDynamicSharedMemorySize, GSMEM);
        cudaFuncSetAttribute(flash_kernel, cudaFuncAttributeMaxDynamicSharedMemorySize, FSMEM);
        cudaStreamCreateWithFlags(&s1, cudaStreamNonBlocking);
        cudaStreamCreateWithFlags(&s2, cudaStreamNonBlocking);
        cudaEventCreateWithFlags(&eFork, cudaEventDisableTiming);
        cudaEventCreateWithFlags(&eW1a,  cudaEventDisableTiming);
        cudaEventCreateWithFlags(&eW2,   cudaEventDisableTiming);
        cudaEventCreateWithFlags(&eXmod, cudaEventDisableTiming);
        cudaEventCreateWithFlags(&eK2b,  cudaEventDisableTiming);
        attr_set = 1;
    }

    // ---- fork: s1 cvt(w1-qkv, w2); s2 cvt(w1-mlp) — concurrent with mod/ln --
    cudaEventRecord(eFork, 0);
    cudaStreamWaitEvent(s1, eFork, 0);
    cudaStreamWaitEvent(s2, eFork, 0);

    cvt_half_kernel<<<((size_t)H3 * HH / 4 + 255) / 256, 256, 0, s1>>>(
        (const float4*)lin1_w, (__half2*)p_w1, H3 * HH / 4);
    cudaEventRecord(eW1a, s1);
    cvt_half_kernel<<<((size_t)HH * HC2 / 4 + 255) / 256, 256, 0, s1>>>(
        (const float4*)lin2_w, (__half2*)p_w2, HH * HC2 / 4);
    cudaEventRecord(eW2, s1);

    cvt_half_kernel<<<((size_t)MLPD * HH / 4 + 255) / 256, 256, 0, s2>>>(
        (const float4*)(lin1_w + (size_t)H3 * HH),
        (__half2*)(p_w1 + (size_t)H3 * HH), MLPD * HH / 4);

    // main: modulation (silu in smem) -> layernorm
    mod_gemm_kernel<<<(BB * H3) / 8, 256>>>(vec, mod_w, mod_b);
    ln_mod_kernel<<<BB * LL, 256>>>(x);
    cudaEventRecord(eXmod, 0);

    // ---- s2: gelu-mlp GEMM (w1-mlp already on s2; wait xmod) ----
    cudaStreamWaitEvent(s2, eXmod, 0);
    hgemm<4><<<dim3(MLPD / GBN, (BB * LL) / GBM), 256, GSMEM, s2>>>(
        p_xmod, HH, p_w1 + (size_t)H3 * HH, HH, p_cat + HH, HC2, HH,
        lin1_b + H3, nullptr, nullptr, nullptr, nullptr);
    cudaEventRecord(eK2b, s2);

    // ---- main: fused qkv GEMM (norm+rope in epilogue) -> flash ----
    cudaStreamWaitEvent(0, eW1a, 0);
    hgemm<2><<<dim3(H3 / GBN, (BB * LL) / GBM), 256, GSMEM>>>(
        p_xmod, HH, p_w1, HH, p_q, HC1, HH, lin1_b, nullptr,
        pe, q_scale, k_scale);
    flash_kernel<<<dim3(LL / 128, BB * NHH), 256, FSMEM>>>();

    // ---- join: lin2 needs flash (program order) + gelu GEMM + w2 ----
    cudaStreamWaitEvent(0, eK2b, 0);
    cudaStreamWaitEvent(0, eW2, 0);
    hgemm<3><<<dim3(HH / GBN, (BB * LL) / GBM), 256, GSMEM>>>(
        p_cat, HC2, p_w2, HC2, out, HH, HC2, lin2_b, x,
        nullptr, nullptr, nullptr);
}

// round 17
// speedup vs baseline: 1.0042x; 1.0042x over previous
#include <cuda_runtime.h>
#include <cuda_fp16.h>
#include <cstdint>
#include <cstddef>

// ---------------------------------------------------------------------------
// SingleStreamBlock: B=2, L=2048, H=2048, NH=16, D=128, MLP=8192
// fp16 tensor cores; fused qkv epilogue (rmsnorm+rope); paired-tile flash;
// chunk-pipelined flash/lin2; dual-stream cvt; split mod (gate off crit path)
// ---------------------------------------------------------------------------
#define BB   2
#define LL   2048
#define HH   2048
#define NHH  16
#define DD   128
#define MLPD 8192
#define H3   6144
#define HC1  14336
#define HC2  10240

// ------------------------- scratch (device globals) ------------------------
__device__ float  g_mod   [BB * H3];
__device__ __half g_xmodh [(size_t)BB * LL * HH];
__device__ __half g_qh    [(size_t)BB * NHH * LL * DD];   // scaled by log2e/sqrt(D)
__device__ __half g_kh    [(size_t)BB * NHH * LL * DD];
__device__ __half g_vh    [(size_t)BB * LL * HH];         // compact V [b][l][n*D+hc]
__device__ __half g_cath  [(size_t)BB * LL * HC2];        // attn|gelu
__device__ __half g_w1h   [(size_t)HC1 * HH];
__device__ __half g_w2h   [(size_t)HH * HC2];

// ------------------------------ helpers ------------------------------------
__device__ __forceinline__ uint32_t smem_u32(const void* p) {
    uint32_t a;
    asm("{ .reg .u64 t; cvta.to.shared.u64 t, %1; cvt.u32.u64 %0, t; }"
        : "=r"(a) : "l"(p));
    return a;
}

__device__ __forceinline__ void cp16(uint32_t s, const void* g) {
    asm volatile("cp.async.cg.shared.global [%0], [%1], 16;" :: "r"(s), "l"(g));
}

__device__ __forceinline__ void ldsm4(uint32_t* r, uint32_t addr) {
    asm volatile("ldmatrix.sync.aligned.m8n8.x4.shared.b16 {%0,%1,%2,%3}, [%4];"
        : "=r"(r[0]), "=r"(r[1]), "=r"(r[2]), "=r"(r[3]) : "r"(addr));
}

__device__ __forceinline__ void ldsm4t(uint32_t* r, uint32_t addr) {
    asm volatile("ldmatrix.sync.aligned.m8n8.x4.trans.shared.b16 {%0,%1,%2,%3}, [%4];"
        : "=r"(r[0]), "=r"(r[1]), "=r"(r[2]), "=r"(r[3]) : "r"(addr));
}

__device__ __forceinline__ void mma16816(float* d, const uint32_t* a, const uint32_t* b) {
    asm volatile(
        "mma.sync.aligned.m16n8k16.row.col.f32.f16.f16.f32 "
        "{%0,%1,%2,%3}, {%4,%5,%6,%7}, {%8,%9}, {%0,%1,%2,%3};"
        : "+f"(d[0]), "+f"(d[1]), "+f"(d[2]), "+f"(d[3])
        : "r"(a[0]), "r"(a[1]), "r"(a[2]), "r"(a[3]), "r"(b[0]), "r"(b[1]));
}

// ============ fp16 GEMM, 128x256 CTA tile, 256 thr, 64x64 warp tiles ========
// C[M,N] = A[M,K] @ B[N,K]^T
// EPI 2: fused qkv epilogue: q/k -> rmsnorm+rope -> g_qh/g_kh; v -> g_vh
// EPI 3: C fp32 = xres + gate*(v + bias[c])   (chunked M via l_off)
// EPI 4: C half = gelu(v + bias[c])
#define GBM 128
#define GBN 256
#define GBK 64
#define GSTG 4
#define GA_BYTES (GBM * 128)
#define GB_BYTES (GBN * 128)
#define GSTAGE (GA_BYTES + GB_BYTES)
#define GSMEM (GSTG * GSTAGE)         // 196608

__device__ __forceinline__ void gstage_load(uint32_t sbuf,
                                            const __half* __restrict__ A, int lda,
                                            const __half* __restrict__ B, int ldb,
                                            int m0, int n0, int kt, int tid) {
    const __half* Ab = A + (size_t)m0 * lda + kt * GBK;
#pragma unroll
    for (int i = 0; i < 4; i++) {
        int idx = tid + i * 256;
        int r = idx >> 3, c = idx & 7;
        cp16(sbuf + r * 128 + ((c << 4) ^ ((r & 7) << 4)),
             Ab + (size_t)r * lda + c * 8);
    }
    const __half* Bb = B + (size_t)n0 * ldb + kt * GBK;
#pragma unroll
    for (int i = 0; i < 8; i++) {
        int idx = tid + i * 256;
        int r = idx >> 3, c = idx & 7;
        cp16(sbuf + GA_BYTES + r * 128 + ((c << 4) ^ ((r & 7) << 4)),
             Bb + (size_t)r * ldb + c * 8);
    }
}

template<int EPI>
__global__ __launch_bounds__(256, 1) void hgemm(
    const __half* __restrict__ A, int lda,
    const __half* __restrict__ B, int ldb,
    void* __restrict__ Cg, int ldc,
    int K,
    const float* __restrict__ bias,
    const float* __restrict__ xres,
    const float* __restrict__ pe,
    const float* __restrict__ qsc,
    const float* __restrict__ ksc,
    int l_off)
{
    extern __shared__ char smem_raw[];
    uint32_t sb = smem_u32(smem_raw);
    int tid = threadIdx.x, lane = tid & 31, w = tid >> 5;
    int wm = w >> 2, wn = w & 3;                 // 2x4 warps, warp tile 64x64

    int m0;
    if (l_off >= 0) {
        int by = blockIdx.y;
        m0 = (by < 8) ? (by * GBM + l_off) : ((by - 8) * GBM + 2048 + l_off);
    } else {
        m0 = blockIdx.y * GBM;
    }
    int n0 = blockIdx.x * GBN;
    int nkt = K / GBK;

#pragma unroll
    for (int t = 0; t < GSTG - 1; t++) {
        gstage_load(sb + t * GSTAGE, A, lda, B, ldb, m0, n0, t, tid);
        asm volatile("cp.async.commit_group;" ::: "memory");
    }

    float acc[4][8][4];
#pragma unroll
    for (int mi = 0; mi < 4; mi++)
#pragma unroll
        for (int ni = 0; ni < 8; ni++)
#pragma unroll
            for (int e = 0; e < 4; e++) acc[mi][ni][e] = 0.f;

    int l15 = lane & 15;
    uint32_t khi = (lane >> 4) << 4;
    uint32_t aoff[4], amask[4];
#pragma unroll
    for (int mi = 0; mi < 4; mi++) {
        int row = wm * 64 + mi * 16 + l15;
        aoff[mi]  = row * 128;
        amask[mi] = (row & 7) << 4;
    }
    uint32_t boff[4], bmask[4];
#pragma unroll
    for (int p = 0; p < 4; p++) {
        int row = wn * 64 + p * 16 + l15;
        boff[p]  = GA_BYTES + row * 128;
        bmask[p] = (row & 7) << 4;
    }

    for (int kt = 0; kt < nkt; kt++) {
        int pend = nkt - kt - 1;
        if (pend > GSTG - 2) pend = GSTG - 2;
        if (pend == 2)      asm volatile("cp.async.wait_group 2;" ::: "memory");
        else if (pend == 1) asm volatile("cp.async.wait_group 1;" ::: "memory");
        else                asm volatile("cp.async.wait_group 0;" ::: "memory");
        __syncthreads();

        int tl = kt + GSTG - 1;
        if (tl < nkt) {
            gstage_load(sb + (tl & (GSTG - 1)) * GSTAGE, A, lda, B, ldb, m0, n0, tl, tid);
            asm volatile("cp.async.commit_group;" ::: "memory");
        }

        uint32_t sA = sb + (kt & (GSTG - 1)) * GSTAGE;
#pragma unroll
        for (int ks = 0; ks < 4; ks++) {
            uint32_t kb = ks * 32 + khi;
            uint32_t a[4][4];
#pragma unroll
            for (int mi = 0; mi < 4; mi++)
                ldsm4(a[mi], sA + aoff[mi] + (kb ^ amask[mi]));
            uint32_t bf[8][2];
#pragma unroll
            for (int p = 0; p < 4; p++) {
                uint32_t r[4];
                ldsm4(r, sA + boff[p] + (kb ^ bmask[p]));
                bf[2 * p][0]     = r[0];
                bf[2 * p + 1][0] = r[1];
                bf[2 * p][1]     = r[2];
                bf[2 * p + 1][1] = r[3];
            }
#pragma unroll
            for (int mi = 0; mi < 4; mi++)
#pragma unroll
                for (int ni = 0; ni < 8; ni++)
                    mma16816(acc[mi][ni], a[mi], bf[ni]);
        }
    }

    int rb = m0 + wm * 64, nb = n0 + wn * 64;
    int r0 = lane >> 2, c0 = (lane & 3) * 2;
    if (EPI == 3) {
        float* C = (float*)Cg;
#pragma unroll
        for (int mi = 0; mi < 4; mi++) {
#pragma unroll
            for (int ni = 0; ni < 8; ni++) {
                int r = rb + mi * 16 + r0;
                int c = nb + ni * 8 + c0;
                int bt = r >> 11;
                float g0 = g_mod[bt * H3 + 2 * HH + c];
                float g1 = g_mod[bt * H3 + 2 * HH + c + 1];
                float b0 = bias[c], b1 = bias[c + 1];
                C[(size_t)r * ldc + c]           = xres[(size_t)r * ldc + c]           + g0 * (acc[mi][ni][0] + b0);
                C[(size_t)r * ldc + c + 1]       = xres[(size_t)r * ldc + c + 1]       + g1 * (acc[mi][ni][1] + b1);
                C[(size_t)(r + 8) * ldc + c]     = xres[(size_t)(r + 8) * ldc + c]     + g0 * (acc[mi][ni][2] + b0);
                C[(size_t)(r + 8) * ldc + c + 1] = xres[(size_t)(r + 8) * ldc + c + 1] + g1 * (acc[mi][ni][3] + b1);
            }
        }
    } else if (EPI == 2) {
        if (n0 >= 4096) {
            // ---- V region: plain bias, compact layout ----
#pragma unroll
            for (int mi = 0; mi < 4; mi++) {
#pragma unroll
                for (int ni = 0; ni < 8; ni++) {
                    int r = rb + mi * 16 + r0;
                    int c = nb + ni * 8 + c0;
                    float b0 = bias[c], b1 = bias[c + 1];
                    int bb = r >> 11, l = r & 2047;
                    *(__half2*)(g_vh + (size_t)(bb * LL + l) * HH + (c - 4096)) =
                        __floats2half2_rn(acc[mi][ni][0] + b0, acc[mi][ni][1] + b1);
                    *(__half2*)(g_vh + (size_t)(bb * LL + l + 8) * HH + (c - 4096)) =
                        __floats2half2_rn(acc[mi][ni][2] + b0, acc[mi][ni][3] + b1);
                }
            }
        } else {
            // ---- q/k region: rmsnorm + rope fused ----
            __syncthreads();
            float* sums = (float*)smem_raw;        // [128][4]
            int isK = (n0 >= 2048);
#pragma unroll
            for (int mi = 0; mi < 4; mi++) {
                float s0 = 0.f, s1 = 0.f;
#pragma unroll
                for (int ni = 0; ni < 8; ni++) {
                    int c = nb + ni * 8 + c0;
                    float b0 = bias[c], b1 = bias[c + 1];
                    float v0 = acc[mi][ni][0] + b0, v1 = acc[mi][ni][1] + b1;
                    float v2 = acc[mi][ni][2] + b0, v3 = acc[mi][ni][3] + b1;
                    s0 += v0 * v0 + v1 * v1;
                    s1 += v2 * v2 + v3 * v3;
                }
                s0 += __shfl_xor_sync(0xffffffffu, s0, 1);
                s0 += __shfl_xor_sync(0xffffffffu, s0, 2);
                s1 += __shfl_xor_sync(0xffffffffu, s1, 1);
                s1 += __shfl_xor_sync(0xffffffffu, s1, 2);
                if ((lane & 3) == 0) {
                    sums[(wm * 64 + mi * 16 + r0) * 4 + wn]     = s0;
                    sums[(wm * 64 + mi * 16 + r0 + 8) * 4 + wn] = s1;
                }
            }
            __syncthreads();
            const float* scp = isK ? ksc : qsc;
            int hbase = (nb - (isK ? 2048 : 0)) >> 7;
            float qmul = isK ? 1.f : (0.08838834764831845f * 1.4426950408889634f);
            __half* base = isK ? g_kh : g_qh;
#pragma unroll
            for (int mi = 0; mi < 4; mi++) {
#pragma unroll
                for (int e = 0; e < 2; e++) {
                    int r = rb + mi * 16 + r0 + e * 8;
                    int lrow = wm * 64 + mi * 16 + r0 + e * 8;
                    float tot = sums[lrow * 4 + wn] + sums[lrow * 4 + (wn ^ 1)];
                    float rstd = rsqrtf(tot * (1.f / DD) + 1e-6f) * qmul;
                    int bb = r >> 11, l = r & 2047;
                    const float* peb = pe + (size_t)(bb * LL + l) * (DD / 2) * 4;
                    __half* dst = base + ((size_t)(bb * NHH + hbase) * LL + l) * DD;
#pragma unroll
                    for (int ni = 0; ni < 8; ni++) {
                        int c = nb + ni * 8 + c0;
                        int hc = c & 127;
                        float v0 = (acc[mi][ni][e ? 2 : 0] + bias[c])     * rstd * scp[hc];
                        float v1 = (acc[mi][ni][e ? 3 : 1] + bias[c + 1]) * rstd * scp[hc + 1];
                        const float4 p4 = *(const float4*)(peb + (hc >> 1) * 4);
                        float o0 = p4.x * v0 + p4.y * v1;
                        float o1 = p4.z * v0 + p4.w * v1;
                        *(__half2*)(dst + hc) = __floats2half2_rn(o0, o1);
                    }
                }
            }
        }
    } else {
        __half* C = (__half*)Cg;
#pragma unroll
        for (int mi = 0; mi < 4; mi++) {
#pragma unroll
            for (int ni = 0; ni < 8; ni++) {
                int r = rb + mi * 16 + r0;
                int c = nb + ni * 8 + c0;
                float b0 = bias[c], b1 = bias[c + 1];
                float v0 = acc[mi][ni][0] + b0, v1 = acc[mi][ni][1] + b1;
                float v2 = acc[mi][ni][2] + b0, v3 = acc[mi][ni][3] + b1;
                if (EPI == 4) {
                    float t0 = 0.7978845608028654f * (v0 + 0.044715f * v0 * v0 * v0);
                    float t1 = 0.7978845608028654f * (v1 + 0.044715f * v1 * v1 * v1);
                    float t2 = 0.7978845608028654f * (v2 + 0.044715f * v2 * v2 * v2);
                    float t3 = 0.7978845608028654f * (v3 + 0.044715f * v3 * v3 * v3);
                    v0 = 0.5f * v0 * (1.f + tanhf(t0));
                    v1 = 0.5f * v1 * (1.f + tanhf(t1));
                    v2 = 0.5f * v2 * (1.f + tanhf(t2));
                    v3 = 0.5f * v3 * (1.f + tanhf(t3));
                }
                *(__half2*)(C + (size_t)r * ldc + c)       = __floats2half2_rn(v0, v1);
                *(__half2*)(C + (size_t)(r + 8) * ldc + c) = __floats2half2_rn(v2, v3);
            }
        }
    }
}

// ================== flash attention v3: paired-tile softmax =================
#define FKT 64
#define FK_BYTES 16384
#define FNBUF 6
#define FSM_K0 32768
#define FSM_V0 (32768 + FNBUF * FK_BYTES)
#define FSMEM  (32768 + 2 * FNBUF * FK_BYTES)        // 229376

__device__ __forceinline__ uint32_t swoff(int row, int c) {
    return (uint32_t)(row * 256 + ((c >> 3) << 7) + (((c & 7) ^ (row & 7)) << 4));
}

__global__ __launch_bounds__(256, 1) void flash_kernel(int qoff) {
    extern __shared__ char fsm[];
    uint32_t sb = smem_u32(fsm);
    int tid = threadIdx.x, lane = tid & 31, w = tid >> 5;
    int q0 = (blockIdx.x + qoff) * 128;
    int bh = blockIdx.y;
    int b = bh >> 4, h = bh & 15;

    const __half* Qg = g_qh + ((size_t)bh * LL + q0) * DD;
    const __half* Kg = g_kh + (size_t)bh * LL * DD;
    const __half* Vg = g_vh + (size_t)b * LL * HH + h * DD;

    int lr = tid >> 4, lc = tid & 15;

    {
#pragma unroll
        for (int i = 0; i < 8; i++) {
            int r = lr + i * 16;
            cp16(sb + swoff(r, lc), Qg + (size_t)r * DD + lc * 8);
        }
        asm volatile("cp.async.commit_group;" ::: "memory");
    }

#pragma unroll
    for (int t = 0; t < 4; t++) {
        const __half* Kt = Kg + (size_t)t * FKT * DD;
        const __half* Vt = Vg + (size_t)t * FKT * HH;
        uint32_t kdst = sb + FSM_K0 + t * FK_BYTES;
        uint32_t vdst = sb + FSM_V0 + t * FK_BYTES;
#pragma unroll
        for (int i = 0; i < 4; i++) {
            int r = lr + i * 16;
            cp16(kdst + swoff(r, lc), Kt + (size_t)r * DD + lc * 8);
            cp16(vdst + swoff(r, lc), Vt + (size_t)r * HH + lc * 8);
        }
        asm volatile("cp.async.commit_group;" ::: "memory");
    }

    asm volatile("cp.async.wait_group 4;" ::: "memory");
    __syncthreads();

    int l15 = lane & 15;
    int qrow = w * 16 + l15;
    uint32_t qf[8][4];
#pragma unroll
    for (int ks = 0; ks < 8; ks++) {
        int cq = ks * 2 + (lane >> 4);
        ldsm4(qf[ks], sb + swoff(qrow, cq));
    }

    uint32_t voff[8];
#pragma unroll
    for (int p = 0; p < 8; p++) {
        int nc = p * 2 + (lane >> 4);
        voff[p] = (uint32_t)(((nc >> 3) << 7) + (((nc & 7) ^ (l15 & 7)) << 4) + l15 * 256);
    }

    float accO[16][4];
#pragma unroll
    for (int nt = 0; nt < 16; nt++)
#pragma unroll
        for (int e = 0; e < 4; e++) accO[nt][e] = 0.f;
    float m0 = -1e30f, m1 = -1e30f, l0 = 0.f, l1 = 0.f;

    const int NT = LL / FKT;     // 32 tiles, 16 pairs
    for (int pj = 0; pj < NT; pj += 2) {
        if (pj + 2 < NT) asm volatile("cp.async.wait_group 2;" ::: "memory");
        else             asm volatile("cp.async.wait_group 0;" ::: "memory");
        __syncthreads();

        if (pj + 4 < NT) {
#pragma unroll
            for (int t = 0; t < 2; t++) {
                int tl = pj + 4 + t;
                const __half* Kt = Kg + (size_t)tl * FKT * DD;
                const __half* Vt = Vg + (size_t)tl * FKT * HH;
                uint32_t kdst = sb + FSM_K0 + (tl % FNBUF) * FK_BYTES;
                uint32_t vdst = sb + FSM_V0 + (tl % FNBUF) * FK_BYTES;
#pragma unroll
                for (int i = 0; i < 4; i++) {
                    int r = lr + i * 16;
                    cp16(kdst + swoff(r, lc), Kt + (size_t)r * DD + lc * 8);
                    cp16(vdst + swoff(r, lc), Vt + (size_t)r * HH + lc * 8);
                }
                asm volatile("cp.async.commit_group;" ::: "memory");
            }
        }

        uint32_t kb0 = sb + FSM_K0 + (pj % FNBUF) * FK_BYTES;
        uint32_t kb1 = sb + FSM_K0 + ((pj + 1) % FNBUF) * FK_BYTES;
        uint32_t vb0 = sb + FSM_V0 + (pj % FNBUF) * FK_BYTES;
        uint32_t vb1 = sb + FSM_V0 + ((pj + 1) % FNBUF) * FK_BYTES;

        float accS[16][4];
#pragma unroll
        for (int nt = 0; nt < 16; nt++)
#pragma unroll
            for (int e = 0; e < 4; e++) accS[nt][e] = 0.f;

#pragma unroll
        for (int ks = 0; ks < 8; ks++) {
            int cq = ks * 2 + (lane >> 4);
            uint32_t cpart = (uint32_t)(((cq >> 3) << 7) + ((cq & 7) << 4));
#pragma unroll
            for (int half = 0; half < 2; half++) {
                uint32_t kbh = half ? kb1 : kb0;
#pragma unroll
                for (int p = 0; p < 4; p++) {
                    int krow = p * 16 + l15;
                    uint32_t r[4];
                    ldsm4(r, kbh + (uint32_t)(krow * 256)
                              + (cpart ^ ((uint32_t)(krow & 7) << 4)));
                    uint32_t b0[2] = { r[0], r[2] }, b1[2] = { r[1], r[3] };
                    mma16816(accS[half * 8 + 2 * p],     qf[ks], b0);
                    mma16816(accS[half * 8 + 2 * p + 1], qf[ks], b1);
                }
            }
        }

        float rmax0 = accS[0][0], rmax1 = accS[0][2];
#pragma unroll
        for (int nt = 0; nt < 16; nt++) {
            rmax0 = fmaxf(rmax0, fmaxf(accS[nt][0], accS[nt][1]));
            rmax1 = fmaxf(rmax1, fmaxf(accS[nt][2], accS[nt][3]));
        }
        rmax0 = fmaxf(rmax0, __shfl_xor_sync(0xffffffffu, rmax0, 1));
        rmax0 = fmaxf(rmax0, __shfl_xor_sync(0xffffffffu, rmax0, 2));
        rmax1 = fmaxf(rmax1, __shfl_xor_sync(0xffffffffu, rmax1, 1));
        rmax1 = fmaxf(rmax1, __shfl_xor_sync(0xffffffffu, rmax1, 2));

        float mn0 = fmaxf(m0, rmax0), mn1 = fmaxf(m1, rmax1);
        float al0 = exp2f(m0 - mn0), al1 = exp2f(m1 - mn1);
        m0 = mn0; m1 = mn1;

        float rs0 = 0.f, rs1 = 0.f;
#pragma unroll
        for (int nt = 0; nt < 16; nt++) {
            accS[nt][0] = exp2f(accS[nt][0] - mn0);
            accS[nt][1] = exp2f(accS[nt][1] - mn0);
            accS[nt][2] = exp2f(accS[nt][2] - mn1);
            accS[nt][3] = exp2f(accS[nt][3] - mn1);
            rs0 += accS[nt][0] + accS[nt][1];
            rs1 += accS[nt][2] + accS[nt][3];
        }
        rs0 += __shfl_xor_sync(0xffffffffu, rs0, 1);
        rs0 += __shfl_xor_sync(0xffffffffu, rs0, 2);
        rs1 += __shfl_xor_sync(0xffffffffu, rs1, 1);
        rs1 += __shfl_xor_sync(0xffffffffu, rs1, 2);
        l0 = l0 * al0 + rs0;
        l1 = l1 * al1 + rs1;

#pragma unroll
        for (int nt = 0; nt < 16; nt++) {
            accO[nt][0] *= al0; accO[nt][1] *= al0;
            accO[nt][2] *= al1; accO[nt][3] *= al1;
        }

#pragma unroll
        for (int half = 0; half < 2; half++) {
            uint32_t vbh = half ? vb1 : vb0;
#pragma unroll
            for (int kc = 0; kc < 4; kc++) {
                int s0i = half * 8 + 2 * kc;
                uint32_t pf[4];
                {
                    __half2 h0 = __floats2half2_rn(accS[s0i][0],     accS[s0i][1]);
                    __half2 h1 = __floats2half2_rn(accS[s0i][2],     accS[s0i][3]);
                    __half2 h2 = __floats2half2_rn(accS[s0i + 1][0], accS[s0i + 1][1]);
                    __half2 h3 = __floats2half2_rn(accS[s0i + 1][2], accS[s0i + 1][3]);
                    pf[0] = *(uint32_t*)&h0; pf[1] = *(uint32_t*)&h1;
                    pf[2] = *(uint32_t*)&h2; pf[3] = *(uint32_t*)&h3;
                }
                uint32_t vrow = vbh + (uint32_t)(kc * 4096);
#pragma unroll
                for (int p = 0; p < 8; p++) {
                    uint32_t r[4];
                    ldsm4t(r, vrow + voff[p]);
                    uint32_t b0[2] = { r[0], r[1] }, b1[2] = { r[2], r[3] };
                    mma16816(accO[2 * p],     pf, b0);
                    mma16816(accO[2 * p + 1], pf, b1);
                }
            }
        }
    }

    float i0 = 1.f / l0, i1 = 1.f / l1;
    int r0g = q0 + w * 16 + (lane >> 2);
    int cb  = h * DD + (lane & 3) * 2;
#pragma unroll
    for (int nt = 0; nt < 16; nt++) {
        int col = cb + nt * 8;
        *(__half2*)(g_cath + (size_t)(b * LL + r0g) * HC2 + col) =
            __floats2half2_rn(accO[nt][0] * i0, accO[nt][1] * i0);
        *(__half2*)(g_cath + (size_t)(b * LL + r0g + 8) * HC2 + col) =
            __floats2half2_rn(accO[nt][2] * i1, accO[nt][3] * i1);
    }
}

// ---------------------- weight fp32 -> fp16 convert -------------------------
__global__ void cvt_half_kernel(const float4* __restrict__ src,
                                __half2* __restrict__ dst, int n4) {
    int i = blockIdx.x * blockDim.x + threadIdx.x;
    if (i >= n4) return;
    float4 v = src[i];
    dst[2 * i]     = __floats2half2_rn(v.x, v.y);
    dst[2 * i + 1] = __floats2half2_rn(v.z, v.w);
}

// ---- K0: mod[j] = silu(vec) . mod_w[j] + mod_b[j] over j in [jbase, jbase+jcount) ----
__global__ void mod_gemm_kernel(const float* __restrict__ vec,
                                const float* __restrict__ mod_w,
                                const float* __restrict__ mod_b,
                                int jbase, int jcount) {
    __shared__ float sv[HH];
    int tid = threadIdx.x, lane = tid & 31;
    int b = (blockIdx.x * 8) / jcount;             // 8 outputs per CTA
    const float4* vr = (const float4*)(vec + (size_t)b * HH);
#pragma unroll
    for (int i = tid; i < HH / 4; i += 256) {
        float4 v = vr[i];
        float4 o;
        o.x = v.x / (1.f + expf(-v.x));
        o.y = v.y / (1.f + expf(-v.y));
        o.z = v.z / (1.f + expf(-v.z));
        o.w = v.w / (1.f + expf(-v.w));
        ((float4*)sv)[i] = o;
    }
    __syncthreads();

    int j = jbase + (blockIdx.x * 8 + (tid >> 5)) % jcount;
    const float4* wr = (const float4*)(mod_w + (size_t)j * HH);
    const float4* sv4 = (const float4*)sv;
    float acc = 0.f;
#pragma unroll 4
    for (int k = lane; k < HH / 4; k += 32) {
        float4 v = sv4[k];
        float4 ww = wr[k];
        acc += v.x * ww.x + v.y * ww.y + v.z * ww.z + v.w * ww.w;
    }
#pragma unroll
    for (int o = 16; o; o >>= 1) acc += __shfl_xor_sync(0xffffffffu, acc, o);
    if (lane == 0) g_mod[b * H3 + j] = acc + mod_b[j];
}

// -------- K1: x_mod = (1+scale)*LN(x) + shift  (float4 in, fp16 out) --------
__global__ void ln_mod_kernel(const float* __restrict__ x) {
    __shared__ float red[32];
    __shared__ float bval[2];
    int row = blockIdx.x;
    int tid = threadIdx.x;
    int lane = tid & 31, wid = tid >> 5;
    const float4* xr4 = (const float4*)(x + (size_t)row * HH);

    float4 v[2];
    v[0] = xr4[tid];
    v[1] = xr4[tid + 256];
    float s = v[0].x + v[0].y + v[0].z + v[0].w
            + v[1].x + v[1].y + v[1].z + v[1].w;
#pragma unroll
    for (int o = 16; o; o >>= 1) s += __shfl_xor_sync(0xffffffffu, s, o);
    if (lane == 0) red[wid] = s;
    __syncthreads();
    if (tid < 32) {
        float r = (tid < 8) ? red[tid] : 0.f;
#pragma unroll
        for (int o = 4; o; o >>= 1) r += __shfl_xor_sync(0xffffffffu, r, o);
        if (tid == 0) bval[0] = r;
    }
    __syncthreads();
    float mu = bval[0] * (1.f / HH);

    float sq = 0.f;
#pragma unroll
    for (int i = 0; i < 2; i++) {
        float d0 = v[i].x - mu, d1 = v[i].y - mu;
        float d2 = v[i].z - mu, d3 = v[i].w - mu;
        sq += d0 * d0 + d1 * d1 + d2 * d2 + d3 * d3;
    }
#pragma unroll
    for (int o = 16; o; o >>= 1) sq += __shfl_xor_sync(0xffffffffu, sq, o);
    __syncthreads();
    if (lane == 0) red[wid] = sq;
    __syncthreads();
    if (tid < 32) {
        float r = (tid < 8) ? red[tid] : 0.f;
#pragma unroll
        for (int o = 4; o; o >>= 1) r += __shfl_xor_sync(0xffffffffu, r, o);
        if (tid == 0) bval[1] = r;
    }
    __syncthreads();
    float rstd = rsqrtf(bval[1] * (1.f / HH) + 1e-6f);

    int b = row >> 11;
#pragma unroll
    for (int i = 0; i < 2; i++) {
        int c = (tid + i * 256) * 4;
        float4 sc4 = *(const float4*)(g_mod + b * H3 + HH + c);
        float4 sh4 = *(const float4*)(g_mod + b * H3 + c);
        float o0 = (1.f + sc4.x) * ((v[i].x - mu) * rstd) + sh4.x;
        float o1 = (1.f + sc4.y) * ((v[i].y - mu) * rstd) + sh4.y;
        float o2 = (1.f + sc4.z) * ((v[i].z - mu) * rstd) + sh4.z;
        float o3 = (1.f + sc4.w) * ((v[i].w - mu) * rstd) + sh4.w;
        uint2 o;
        *(__half2*)&o.x = __floats2half2_rn(o0, o1);
        *(__half2*)&o.y = __floats2half2_rn(o2, o3);
        *(uint2*)(g_xmodh + (size_t)row * HH + c) = o;
    }
}

// ---------------------------------------------------------------------------
extern "C" void kernel_launch(void* const* d_in, const int* in_sizes, int n_in,
                              void* d_out, int out_size) {
    const float* x       = (const float*)d_in[0];
    const float* vec     = (const float*)d_in[1];
    const float* pe      = (const float*)d_in[2];
    const float* mod_w   = (const float*)d_in[3];
    const float* mod_b   = (const float*)d_in[4];
    const float* lin1_w  = (const float*)d_in[5];
    const float* lin1_b  = (const float*)d_in[6];
    const float* lin2_w  = (const float*)d_in[7];
    const float* lin2_b  = (const float*)d_in[8];
    const float* q_scale = (const float*)d_in[9];
    const float* k_scale = (const float*)d_in[10];
    float* out = (float*)d_out;

    void* tmp;
    cudaGetSymbolAddress(&tmp, g_xmodh);  __half* p_xmod = (__half*)tmp;
    cudaGetSymbolAddress(&tmp, g_cath);   __half* p_cat  = (__half*)tmp;
    cudaGetSymbolAddress(&tmp, g_qh);     __half* p_q    = (__half*)tmp;
    cudaGetSymbolAddress(&tmp, g_w1h);    __half* p_w1   = (__half*)tmp;
    cudaGetSymbolAddress(&tmp, g_w2h);    __half* p_w2   = (__half*)tmp;

    static cudaStream_t s1 = nullptr, s2 = nullptr;
    static cudaEvent_t eFork, eW1a, eW2, eXmod, eK2b, eF1, eL2a;
    static int attr_set = 0;
    if (!attr_set) {
        cudaFuncSetAttribute(hgemm<2>, cudaFuncAttributeMaxDynamicSharedMemorySize, GSMEM);
        cudaFuncSetAttribute(hgemm<3>, cudaFuncAttributeMaxDynamicSharedMemorySize, GSMEM);
        cudaFuncSetAttribute(hgemm<4>, cudaFuncAttributeMaxDynamicSharedMemorySize, GSMEM);
        cudaFuncSetAttribute(flash_kernel, cudaFuncAttributeMaxDynamicSharedMemorySize, FSMEM);
        cudaStreamCreateWithFlags(&s1, cudaStreamNonBlocking);
        cudaStreamCreateWithFlags(&s2, cudaStreamNonBlocking);
        cudaEventCreateWithFlags(&eFork, cudaEventDisableTiming);
        cudaEventCreateWithFlags(&eW1a,  cudaEventDisableTiming);
        cudaEventCreateWithFlags(&eW2,   cudaEventDisableTiming);
        cudaEventCreateWithFlags(&eXmod, cudaEventDisableTiming);
        cudaEventCreateWithFlags(&eK2b,  cudaEventDisableTiming);
        cudaEventCreateWithFlags(&eF1,   cudaEventDisableTiming);
        cudaEventCreateWithFlags(&eL2a,  cudaEventDisableTiming);
        attr_set = 1;
    }

    // ---- fork: s1 cvt(w1-qkv) -> gate-mod -> cvt(w2); s2 cvt(w1-mlp) ----
    cudaEventRecord(eFork, 0);
    cudaStreamWaitEvent(s1, eFork, 0);
    cudaStreamWaitEvent(s2, eFork, 0);

    cvt_half_kernel<<<((size_t)H3 * HH / 4 + 255) / 256, 256, 0, s1>>>(
        (const float4*)lin1_w, (__half2*)p_w1, H3 * HH / 4);
    cudaEventRecord(eW1a, s1);
    // gate third of mod (only needed by lin2 epilogue; ordered before eW2)
    mod_gemm_kernel<<<(BB * HH) / 8, 256, 0, s1>>>(vec, mod_w, mod_b, 2 * HH, HH);
    cvt_half_kernel<<<((size_t)HH * HC2 / 4 + 255) / 256, 256, 0, s1>>>(
        (const float4*)lin2_w, (__half2*)p_w2, HH * HC2 / 4);
    cudaEventRecord(eW2, s1);

    cvt_half_kernel<<<((size_t)MLPD * HH / 4 + 255) / 256, 256, 0, s2>>>(
        (const float4*)(lin1_w + (size_t)H3 * HH),
        (__half2*)(p_w1 + (size_t)H3 * HH), MLPD * HH / 4);

    // main: shift+scale mod -> layernorm
    mod_gemm_kernel<<<(BB * 2 * HH) / 8, 256>>>(vec, mod_w, mod_b, 0, 2 * HH);
    ln_mod_kernel<<<BB * LL, 256>>>(x);
    cudaEventRecord(eXmod, 0);

    // ---- s2: gelu-mlp GEMM (w1-mlp already on s2; wait xmod) ----
    cudaStreamWaitEvent(s2, eXmod, 0);
    hgemm<4><<<dim3(MLPD / GBN, (BB * LL) / GBM), 256, GSMEM, s2>>>(
        p_xmod, HH, p_w1 + (size_t)H3 * HH, HH, p_cat + HH, HC2, HH,
        lin1_b + H3, nullptr, nullptr, nullptr, nullptr, -1);
    cudaEventRecord(eK2b, s2);

    // ---- main: fused qkv GEMM -> flash chunk 1 (rows l<1024) ----
    cudaStreamWaitEvent(0, eW1a, 0);
    hgemm<2><<<dim3(H3 / GBN, (BB * LL) / GBM), 256, GSMEM>>>(
        p_xmod, HH, p_w1, HH, p_q, HC1, HH, lin1_b, nullptr,
        pe, q_scale, k_scale, -1);
    flash_kernel<<<dim3(8, BB * NHH), 256, FSMEM>>>(0);
    cudaEventRecord(eF1, 0);
    flash_kernel<<<dim3(8, BB * NHH), 256, FSMEM>>>(8);

    // ---- s2: lin2 chunk 1 (rows l<1024) after gelu + flash c1 + w2(+gate) --
    cudaStreamWaitEvent(s2, eF1, 0);
    cudaStreamWaitEvent(s2, eW2, 0);
    hgemm<3><<<dim3(HH / GBN, 16), 256, GSMEM, s2>>>(
        p_cat, HC2, p_w2, HC2, out, HH, HC2, lin2_b, x,
        nullptr, nullptr, nullptr, 0);
    cudaEventRecord(eL2a, s2);

    // ---- main: lin2 chunk 2 (rows l>=1024) after flash c2 + gelu + w2 ----
    cudaStreamWaitEvent(0, eK2b, 0);
    cudaStreamWaitEvent(0, eW2, 0);
    hgemm<3><<<dim3(HH / GBN, 16), 256, GSMEM>>>(
        p_cat, HC2, p_w2, HC2, out, HH, HC2, lin2_b, x,
        nullptr, nullptr, nullptr, 1024);
    cudaStreamWaitEvent(0, eL2a, 0);
}